// round 1
// baseline (speedup 1.0000x reference)
#include <cuda_runtime.h>
#include <math.h>

#define NN 8192
#define DD 1152
#define EE 262144

// -------- scratch (allocation-free: static device globals) --------
__device__ float g_q[(size_t)NN * DD];
__device__ float g_k[(size_t)NN * DD];
__device__ float g_v[(size_t)NN * DD];
__device__ float g_o[(size_t)NN * DD];

// ====================== rot kernel ======================
__global__ void rot_kernel(const float* __restrict__ ev,
                           const float* __restrict__ er,
                           float* __restrict__ rot)
{
    int e = blockIdx.x * 256 + threadIdx.x;
    if (e >= EE) return;
    float vx = ev[3*e+0], vy = ev[3*e+1], vz = ev[3*e+2];
    float dist = sqrtf(vx*vx + vy*vy + vz*vz);
    float nx0 = vx/dist, nx1 = vy/dist, nx2 = vz/dist;

    float r0 = er[3*e+0]-0.5f, r1 = er[3*e+1]-0.5f, r2 = er[3*e+2]-0.5f;
    float rn = sqrtf(r0*r0 + r1*r1 + r2*r2);
    float a0 = r0/rn, a1 = r1/rn, a2 = r2/rn;
    float b0 = -a1, b1 = a0, b2 = a2;       // e2b
    float c0 = a0, c1 = -a2, c2 = a1;       // e2c

    float da = fabsf(a0*nx0 + a1*nx1 + a2*nx2);
    float db = fabsf(b0*nx0 + b1*nx1 + b2*nx2);
    float dc = fabsf(c0*nx0 + c1*nx1 + c2*nx2);

    float e0 = a0, e1 = a1, e2c_ = a2, dcur = da;
    if (dcur > db) { e0 = b0; e1 = b1; e2c_ = b2; dcur = db; }
    if (dcur > dc) { e0 = c0; e1 = c1; e2c_ = c2; }

    // nz = nx x e2, normalized
    float z0 = nx1*e2c_ - nx2*e1;
    float z1 = nx2*e0   - nx0*e2c_;
    float z2 = nx0*e1   - nx1*e0;
    float zn = sqrtf(z0*z0 + z1*z1 + z2*z2);
    z0 /= zn; z1 /= zn; z2 /= zn;
    // ny = nx x nz, normalized
    float y0 = nx1*z2 - nx2*z1;
    float y1 = nx2*z0 - nx0*z2;
    float y2 = nx0*z1 - nx1*z0;
    float yn = sqrtf(y0*y0 + y1*y1 + y2*y2);
    y0 /= yn; y1 /= yn; y2 /= yn;

    float* R = rot + (size_t)e * 9;
    R[0] =  z0; R[1] =  z1; R[2] =  z2;   // row 0: nz
    R[3] = nx0; R[4] = nx1; R[5] = nx2;   // row 1: nx
    R[6] = -y0; R[7] = -y1; R[8] = -y2;   // row 2: -ny
}

// ====================== irreps linear ======================
// y[n, s + o*d + m] = (1/sqrt(128)) * sum_c W[l,o,c] * x[n, s + c*d + m]
// block: 16 nodes, 256 threads = 16x16; thread computes d x 8 outputs.
template<int L>
__global__ void __launch_bounds__(256) linear_kernel(const float* __restrict__ x,
                                                     const float* __restrict__ W,
                                                     float* __restrict__ y)
{
    constexpr int d = 2*L + 1;
    constexpr int s = (L == 0) ? 0 : (L == 1 ? 128 : 512);
    constexpr int rowlen = 128 * d;

    extern __shared__ float sm[];
    float* Ws = sm;                 // [128][132]  Ws[c*132+o] = W[l][o][c]
    float* Xs = sm + 128*132;       // [16][rowlen]

    const int tid = threadIdx.x;
    const int n0  = blockIdx.x * 16;

    const float* Wl = W + L * 16384;
    for (int idx = tid; idx < 16384; idx += 256) {
        int o = idx >> 7, c = idx & 127;
        Ws[c*132 + o] = Wl[idx];
    }
    constexpr int nf4 = 16 * (rowlen/4);
    for (int i = tid; i < nf4; i += 256) {
        int n  = i / (rowlen/4);
        int cs = (i % (rowlen/4)) * 4;
        *(float4*)&Xs[n*rowlen + cs] =
            *(const float4*)&x[(size_t)(n0+n)*DD + s + cs];
    }
    __syncthreads();

    const int ty = tid >> 4, tx = tid & 15;
    float acc[d][8];
    #pragma unroll
    for (int i = 0; i < d; i++)
        #pragma unroll
        for (int j = 0; j < 8; j++) acc[i][j] = 0.f;

    const float* Xrow = Xs + ty * rowlen;
    #pragma unroll 2
    for (int c = 0; c < 128; c++) {
        float xa[d];
        #pragma unroll
        for (int i = 0; i < d; i++) xa[i] = Xrow[c*d + i];
        float4 w0 = *(float4*)&Ws[c*132 + tx*8];
        float4 w1 = *(float4*)&Ws[c*132 + tx*8 + 4];
        float wb[8] = {w0.x, w0.y, w0.z, w0.w, w1.x, w1.y, w1.z, w1.w};
        #pragma unroll
        for (int i = 0; i < d; i++)
            #pragma unroll
            for (int j = 0; j < 8; j++)
                acc[i][j] = fmaf(xa[i], wb[j], acc[i][j]);
    }

    const float scale = 0.08838834764831845f;  // 1/sqrt(128)
    float* yrow = y + (size_t)(n0 + ty) * DD + s;
    #pragma unroll
    for (int j = 0; j < 8; j++) {
        int o = tx*8 + j;
        #pragma unroll
        for (int i = 0; i < d; i++)
            yrow[o*d + i] = acc[i][j] * scale;
    }
}

// ====================== flash attention ======================
// grid: (8 q-tiles, 128 b*h). BM=BK=64, hd=144. 256 threads = 16x16.
__global__ void __launch_bounds__(256) attn_kernel(const float* __restrict__ q,
                                                   const float* __restrict__ k,
                                                   const float* __restrict__ v,
                                                   float* __restrict__ o)
{
    extern __shared__ float sm[];
    float* QsT = sm;               // [144][65]
    float* KsT = QsT + 144*65;     // [144][65]
    float* Vs  = KsT + 144*65;     // [64][148]
    float* Ps  = Vs  + 64*148;     // [64][65]

    const int tid = threadIdx.x;
    const int ty = tid >> 4, tx = tid & 15;
    const int b = blockIdx.y >> 3, h = blockIdx.y & 7;
    const int q0 = blockIdx.x * 64;
    const size_t hoff  = (size_t)h * 144;
    const size_t bbase = (size_t)b * 512;

    const float qscale = 1.0f / 12.0f;  // 1/sqrt(144)
    for (int f = tid; f < 64*36; f += 256) {
        int row = f / 36, cs = (f % 36) * 4;
        float4 qa = *(const float4*)&q[(bbase + q0 + row) * DD + hoff + cs];
        QsT[(cs+0)*65 + row] = qa.x * qscale;
        QsT[(cs+1)*65 + row] = qa.y * qscale;
        QsT[(cs+2)*65 + row] = qa.z * qscale;
        QsT[(cs+3)*65 + row] = qa.w * qscale;
    }

    float m_i[4], l_i[4], oacc[4][9];
    #pragma unroll
    for (int i = 0; i < 4; i++) {
        m_i[i] = -1e30f; l_i[i] = 0.f;
        #pragma unroll
        for (int j = 0; j < 9; j++) oacc[i][j] = 0.f;
    }

    for (int kt = 0; kt < 512; kt += 64) {
        __syncthreads();
        for (int f = tid; f < 64*36; f += 256) {
            int row = f / 36, cs = (f % 36) * 4;
            size_t g = (bbase + kt + row) * (size_t)DD + hoff + cs;
            float4 ka = *(const float4*)&k[g];
            KsT[(cs+0)*65 + row] = ka.x;
            KsT[(cs+1)*65 + row] = ka.y;
            KsT[(cs+2)*65 + row] = ka.z;
            KsT[(cs+3)*65 + row] = ka.w;
            float4 va = *(const float4*)&v[g];
            *(float4*)&Vs[row*148 + cs] = va;
        }
        __syncthreads();

        float s_[4][4];
        #pragma unroll
        for (int i = 0; i < 4; i++)
            #pragma unroll
            for (int j = 0; j < 4; j++) s_[i][j] = 0.f;

        #pragma unroll 2
        for (int c = 0; c < 144; c++) {
            float qa[4], kb[4];
            #pragma unroll
            for (int i = 0; i < 4; i++) qa[i] = QsT[c*65 + 4*ty + i];
            #pragma unroll
            for (int j = 0; j < 4; j++) kb[j] = KsT[c*65 + 4*tx + j];
            #pragma unroll
            for (int i = 0; i < 4; i++)
                #pragma unroll
                for (int j = 0; j < 4; j++)
                    s_[i][j] = fmaf(qa[i], kb[j], s_[i][j]);
        }

        // online softmax (rows 4*ty+i, reduce across 16 tx lanes)
        #pragma unroll
        for (int i = 0; i < 4; i++) {
            float rm = fmaxf(fmaxf(s_[i][0], s_[i][1]), fmaxf(s_[i][2], s_[i][3]));
            #pragma unroll
            for (int off = 8; off; off >>= 1)
                rm = fmaxf(rm, __shfl_xor_sync(0xffffffffu, rm, off));
            float newm = fmaxf(m_i[i], rm);
            float p[4], rs = 0.f;
            #pragma unroll
            for (int j = 0; j < 4; j++) { p[j] = __expf(s_[i][j] - newm); rs += p[j]; }
            #pragma unroll
            for (int off = 8; off; off >>= 1)
                rs += __shfl_xor_sync(0xffffffffu, rs, off);
            float corr = __expf(m_i[i] - newm);
            l_i[i] = l_i[i] * corr + rs;
            m_i[i] = newm;
            #pragma unroll
            for (int j = 0; j < 9; j++) oacc[i][j] *= corr;
            #pragma unroll
            for (int j = 0; j < 4; j++) Ps[(4*ty+i)*65 + 4*tx + j] = p[j];
        }
        __syncthreads();

        #pragma unroll 2
        for (int kk = 0; kk < 64; kk++) {
            float pr[4], vv[9];
            #pragma unroll
            for (int i = 0; i < 4; i++) pr[i] = Ps[(4*ty+i)*65 + kk];
            #pragma unroll
            for (int j = 0; j < 9; j++) vv[j] = Vs[kk*148 + tx*9 + j];
            #pragma unroll
            for (int i = 0; i < 4; i++)
                #pragma unroll
                for (int j = 0; j < 9; j++)
                    oacc[i][j] = fmaf(pr[i], vv[j], oacc[i][j]);
        }
    }

    #pragma unroll
    for (int i = 0; i < 4; i++) {
        float inv = 1.0f / l_i[i];
        size_t base = (bbase + q0 + 4*ty + i) * (size_t)DD + hoff + tx*9;
        #pragma unroll
        for (int j = 0; j < 9; j++) o[base + j] = oacc[i][j] * inv;
    }
}

// ====================== epilogue: residual + LN(first 128) + SiLU ======================
__global__ void __launch_bounds__(256) epilogue_kernel(const float* __restrict__ x,
                                                       const float* __restrict__ attn,
                                                       const float* __restrict__ gamma,
                                                       const float* __restrict__ beta,
                                                       float* __restrict__ out)
{
    const int n = blockIdx.x;
    const int tid = threadIdx.x;
    const size_t base = (size_t)n * DD;

    __shared__ float red[8];
    __shared__ float mu_s, rv_s;

    float val = 0.f;
    if (tid < 128) val = x[base + tid] + attn[base + tid];
    float s1 = val, s2 = val * val;
    #pragma unroll
    for (int off = 16; off; off >>= 1) {
        s1 += __shfl_xor_sync(0xffffffffu, s1, off);
        s2 += __shfl_xor_sync(0xffffffffu, s2, off);
    }
    if (tid < 128 && (tid & 31) == 0) { red[(tid>>5)*2] = s1; red[(tid>>5)*2+1] = s2; }
    __syncthreads();
    if (tid == 0) {
        float t1 = red[0] + red[2] + red[4] + red[6];
        float t2 = red[1] + red[3] + red[5] + red[7];
        float mu = t1 * (1.f/128.f);
        float var = t2 * (1.f/128.f) - mu*mu;
        mu_s = mu;
        rv_s = rsqrtf(var + 1e-5f);
    }
    __syncthreads();
    const float mu = mu_s, rv = rv_s;

    for (int i = tid; i < DD; i += 256) {
        float vv = x[base + i] + attn[base + i];
        if (i < 128) {
            float z = (vv - mu) * rv * gamma[i] + beta[i];
            vv = z / (1.f + __expf(-z));
        }
        out[base + i] = vv;
    }
}

// ====================== launch ======================
extern "C" void kernel_launch(void* const* d_in, const int* in_sizes, int n_in,
                              void* d_out, int out_size)
{
    const float* x     = (const float*)d_in[0];
    const float* ev    = (const float*)d_in[1];
    const float* er    = (const float*)d_in[2];
    const float* Wq    = (const float*)d_in[3];
    const float* Wk    = (const float*)d_in[4];
    const float* Wv    = (const float*)d_in[5];
    const float* Wo    = (const float*)d_in[6];
    const float* gamma = (const float*)d_in[7];
    const float* beta  = (const float*)d_in[8];
    float* out  = (float*)d_out;
    float* rotp = out + (size_t)NN * DD;

    float *qp, *kp, *vp, *op;
    cudaGetSymbolAddress((void**)&qp, g_q);
    cudaGetSymbolAddress((void**)&kp, g_k);
    cudaGetSymbolAddress((void**)&vp, g_v);
    cudaGetSymbolAddress((void**)&op, g_o);

    const int SM0 = 128*132*4 + 16*128*4;   // 75776
    const int SM1 = 128*132*4 + 16*384*4;   // 92160
    const int SM2 = 128*132*4 + 16*640*4;   // 108544
    const int SMA = (144*65*2 + 64*148 + 64*65) * 4;  // 129408

    cudaFuncSetAttribute((const void*)linear_kernel<0>, cudaFuncAttributeMaxDynamicSharedMemorySize, SM0);
    cudaFuncSetAttribute((const void*)linear_kernel<1>, cudaFuncAttributeMaxDynamicSharedMemorySize, SM1);
    cudaFuncSetAttribute((const void*)linear_kernel<2>, cudaFuncAttributeMaxDynamicSharedMemorySize, SM2);
    cudaFuncSetAttribute((const void*)attn_kernel,      cudaFuncAttributeMaxDynamicSharedMemorySize, SMA);

    rot_kernel<<<EE/256, 256>>>(ev, er, rotp);

    linear_kernel<0><<<NN/16, 256, SM0>>>(x, Wq, qp);
    linear_kernel<1><<<NN/16, 256, SM1>>>(x, Wq, qp);
    linear_kernel<2><<<NN/16, 256, SM2>>>(x, Wq, qp);
    linear_kernel<0><<<NN/16, 256, SM0>>>(x, Wk, kp);
    linear_kernel<1><<<NN/16, 256, SM1>>>(x, Wk, kp);
    linear_kernel<2><<<NN/16, 256, SM2>>>(x, Wk, kp);
    linear_kernel<0><<<NN/16, 256, SM0>>>(x, Wv, vp);
    linear_kernel<1><<<NN/16, 256, SM1>>>(x, Wv, vp);
    linear_kernel<2><<<NN/16, 256, SM2>>>(x, Wv, vp);

    attn_kernel<<<dim3(8, 128), 256, SMA>>>(qp, kp, vp, op);

    // attn_out -> reuse g_k
    linear_kernel<0><<<NN/16, 256, SM0>>>(op, Wo, kp);
    linear_kernel<1><<<NN/16, 256, SM1>>>(op, Wo, kp);
    linear_kernel<2><<<NN/16, 256, SM2>>>(op, Wo, kp);

    epilogue_kernel<<<NN, 256>>>(x, kp, gamma, beta, out);
}

// round 2
// speedup vs baseline: 1.3299x; 1.3299x over previous
#include <cuda_runtime.h>
#include <math.h>

#define NN 8192
#define DD 1152
#define EE 262144

// -------- scratch (allocation-free: static device globals) --------
__device__ float g_q[(size_t)NN * DD];
__device__ float g_k[(size_t)NN * DD];
__device__ float g_v[(size_t)NN * DD];
__device__ float g_o[(size_t)NN * DD];

// -------- packed f32x2 helpers (Blackwell FFMA2 path) --------
typedef unsigned long long ull;

__device__ __forceinline__ void fma2(ull& acc, ull a, ull b) {
    asm("fma.rn.f32x2 %0, %1, %2, %0;" : "+l"(acc) : "l"(a), "l"(b));
}
__device__ __forceinline__ void mul2(ull& a, ull b) {
    asm("mul.rn.f32x2 %0, %0, %1;" : "+l"(a) : "l"(b));
}
__device__ __forceinline__ ull bcast2(float x) {
    ull r; asm("mov.b64 %0, {%1, %1};" : "=l"(r) : "f"(x)); return r;
}
__device__ __forceinline__ ull pack2(float lo, float hi) {
    ull r; asm("mov.b64 %0, {%1, %2};" : "=l"(r) : "f"(lo), "f"(hi)); return r;
}
__device__ __forceinline__ void unpack2(ull v, float& lo, float& hi) {
    asm("mov.b64 {%0, %1}, %2;" : "=f"(lo), "=f"(hi) : "l"(v));
}

// ====================== rot kernel ======================
__global__ void rot_kernel(const float* __restrict__ ev,
                           const float* __restrict__ er,
                           float* __restrict__ rot)
{
    int e = blockIdx.x * 256 + threadIdx.x;
    if (e >= EE) return;
    float vx = ev[3*e+0], vy = ev[3*e+1], vz = ev[3*e+2];
    float dist = sqrtf(vx*vx + vy*vy + vz*vz);
    float nx0 = vx/dist, nx1 = vy/dist, nx2 = vz/dist;

    float r0 = er[3*e+0]-0.5f, r1 = er[3*e+1]-0.5f, r2 = er[3*e+2]-0.5f;
    float rn = sqrtf(r0*r0 + r1*r1 + r2*r2);
    float a0 = r0/rn, a1 = r1/rn, a2 = r2/rn;
    float b0 = -a1, b1 = a0, b2 = a2;
    float c0 = a0, c1 = -a2, c2 = a1;

    float da = fabsf(a0*nx0 + a1*nx1 + a2*nx2);
    float db = fabsf(b0*nx0 + b1*nx1 + b2*nx2);
    float dc = fabsf(c0*nx0 + c1*nx1 + c2*nx2);

    float e0 = a0, e1 = a1, e2c_ = a2, dcur = da;
    if (dcur > db) { e0 = b0; e1 = b1; e2c_ = b2; dcur = db; }
    if (dcur > dc) { e0 = c0; e1 = c1; e2c_ = c2; }

    float z0 = nx1*e2c_ - nx2*e1;
    float z1 = nx2*e0   - nx0*e2c_;
    float z2 = nx0*e1   - nx1*e0;
    float zn = sqrtf(z0*z0 + z1*z1 + z2*z2);
    z0 /= zn; z1 /= zn; z2 /= zn;
    float y0 = nx1*z2 - nx2*z1;
    float y1 = nx2*z0 - nx0*z2;
    float y2 = nx0*z1 - nx1*z0;
    float yn = sqrtf(y0*y0 + y1*y1 + y2*y2);
    y0 /= yn; y1 /= yn; y2 /= yn;

    float* R = rot + (size_t)e * 9;
    R[0] =  z0; R[1] =  z1; R[2] =  z2;
    R[3] = nx0; R[4] = nx1; R[5] = nx2;
    R[6] = -y0; R[7] = -y1; R[8] = -y2;
}

// ====================== irreps linear ======================
// y[n, s + o*d + m] = (1/sqrt(128)) * sum_c W[l,o,c] * x[n, s + c*d + m]
// grid (NN/16, 2): 16 nodes, half the outputs (64) per block. 256 thr = 16x16.
// X stored transposed in smem: XsT[(n*d+m)][c], so c is vector dim.
template<int L>
__global__ void __launch_bounds__(256) linear_kernel(const float* __restrict__ x,
                                                     const float* __restrict__ W,
                                                     float* __restrict__ y)
{
    constexpr int d = 2*L + 1;
    constexpr int s = (L == 0) ? 0 : (L == 1 ? 128 : 512);
    constexpr int rowlen = 128 * d;

    extern __shared__ float sm[];
    float* Ws  = sm;            // [128][68]: Ws[c*68+oo] = W[l][obase+oo][c]
    float* XsT = sm + 128*68;   // [16*d][128]

    const int tid = threadIdx.x;
    const int n0  = blockIdx.x * 16;
    const int obase = blockIdx.y * 64;

    const float* Wl = W + L * 16384 + obase * 128;
    for (int idx = tid; idx < 8192; idx += 256) {
        int o = idx >> 7, c = idx & 127;
        Ws[c*68 + o] = Wl[o*128 + c];
    }
    for (int i = tid; i < 16 * (rowlen/4); i += 256) {
        int n = i / (rowlen/4);
        int p = (i % (rowlen/4)) * 4;
        float4 v4 = *(const float4*)&x[(size_t)(n0+n)*DD + s + p];
        float vv[4] = {v4.x, v4.y, v4.z, v4.w};
        #pragma unroll
        for (int e = 0; e < 4; e++) {
            int pp = p + e, c = pp / d, m = pp - c * d;
            XsT[(n*d + m)*128 + c] = vv[e];
        }
    }
    __syncthreads();

    const int ty = tid >> 4, tx = tid & 15;
    ull acc[d][2];
    #pragma unroll
    for (int m = 0; m < d; m++) { acc[m][0] = 0ull; acc[m][1] = 0ull; }

    const float* Xbase = XsT + ty * d * 128;
    for (int c = 0; c < 128; c += 4) {
        float4 xa[d];
        #pragma unroll
        for (int m = 0; m < d; m++) xa[m] = *(const float4*)&Xbase[m*128 + c];
        #pragma unroll
        for (int cc = 0; cc < 4; cc++) {
            float4 w = *(const float4*)&Ws[(c+cc)*68 + tx*4];
            ull w01 = pack2(w.x, w.y), w23 = pack2(w.z, w.w);
            #pragma unroll
            for (int m = 0; m < d; m++) {
                float xs = ((const float*)&xa[m])[cc];
                ull xb = bcast2(xs);
                fma2(acc[m][0], xb, w01);
                fma2(acc[m][1], xb, w23);
            }
        }
    }

    const float scale = 0.08838834764831845f;  // 1/sqrt(128)
    float* yrow = y + (size_t)(n0 + ty) * DD + s;
    #pragma unroll
    for (int m = 0; m < d; m++) {
        #pragma unroll
        for (int jp = 0; jp < 2; jp++) {
            float f0, f1; unpack2(acc[m][jp], f0, f1);
            int o = obase + tx*4 + jp*2;
            yrow[(o  )*d + m] = f0 * scale;
            yrow[(o+1)*d + m] = f1 * scale;
        }
    }
}

// ====================== flash attention (f32x2) ======================
// grid (8 q-tiles, 128 b*h). BM=BK=64, hd=144 (padded to 160 for V/O).
// 256 threads = 16(ty: 4 q-rows each) x 16(tx: 4 k-cols in S / 10 O-cols in PV)
__global__ void __launch_bounds__(256) attn_kernel(const float* __restrict__ q,
                                                   const float* __restrict__ k,
                                                   const float* __restrict__ v,
                                                   float* __restrict__ o)
{
    extern __shared__ float sm[];
    float* QsT = sm;               // [144][68]
    float* KsT = QsT + 144*68;     // [144][68]
    float* Vs  = KsT + 144*68;     // [64][160]  (cols 144..159 = 0 pad)
    float* PsT = Vs  + 64*160;     // [64 kk][68 rows]

    const int tid = threadIdx.x;
    const int ty = tid >> 4, tx = tid & 15;
    const int b = blockIdx.y >> 3, h = blockIdx.y & 7;
    const int q0 = blockIdx.x * 64;
    const size_t hoff  = (size_t)h * 144;
    const size_t bbase = (size_t)b * 512;

    const float qscale = 1.0f / 12.0f;  // 1/sqrt(144)
    for (int f = tid; f < 64*36; f += 256) {
        int row = f / 36, cs = (f % 36) * 4;
        float4 qa = *(const float4*)&q[(bbase + q0 + row) * DD + hoff + cs];
        QsT[(cs+0)*68 + row] = qa.x * qscale;
        QsT[(cs+1)*68 + row] = qa.y * qscale;
        QsT[(cs+2)*68 + row] = qa.z * qscale;
        QsT[(cs+3)*68 + row] = qa.w * qscale;
    }
    // zero the V pad region once (cols 144..159 of each of 64 rows)
    {
        int row = tid >> 2, cs = 144 + (tid & 3) * 4;
        *(float4*)&Vs[row*160 + cs] = make_float4(0.f, 0.f, 0.f, 0.f);
    }

    float m_i[4], l_i[4];
    ull oacc[4][5];
    #pragma unroll
    for (int i = 0; i < 4; i++) {
        m_i[i] = -1e30f; l_i[i] = 0.f;
        #pragma unroll
        for (int jp = 0; jp < 5; jp++) oacc[i][jp] = 0ull;
    }

    for (int kt = 0; kt < 512; kt += 64) {
        __syncthreads();
        for (int f = tid; f < 64*36; f += 256) {
            int row = f / 36, cs = (f % 36) * 4;
            size_t g = (bbase + kt + row) * (size_t)DD + hoff + cs;
            float4 ka = *(const float4*)&k[g];
            KsT[(cs+0)*68 + row] = ka.x;
            KsT[(cs+1)*68 + row] = ka.y;
            KsT[(cs+2)*68 + row] = ka.z;
            KsT[(cs+3)*68 + row] = ka.w;
            float4 va = *(const float4*)&v[g];
            *(float4*)&Vs[row*160 + cs] = va;
        }
        __syncthreads();

        // ---- S = Q K^T, packed over k-col pairs ----
        ull s2[4][2];
        #pragma unroll
        for (int i = 0; i < 4; i++) { s2[i][0] = 0ull; s2[i][1] = 0ull; }

        #pragma unroll 2
        for (int c = 0; c < 144; c++) {
            float4 qa = *(const float4*)&QsT[c*68 + 4*ty];
            float4 kb = *(const float4*)&KsT[c*68 + 4*tx];
            ull k01 = pack2(kb.x, kb.y), k23 = pack2(kb.z, kb.w);
            #pragma unroll
            for (int i = 0; i < 4; i++) {
                ull qb = bcast2(((const float*)&qa)[i]);
                fma2(s2[i][0], qb, k01);
                fma2(s2[i][1], qb, k23);
            }
        }

        // ---- online softmax per row (reduce across 16 tx lanes) ----
        float p_[4][4];
        #pragma unroll
        for (int i = 0; i < 4; i++) {
            float s_[4];
            unpack2(s2[i][0], s_[0], s_[1]);
            unpack2(s2[i][1], s_[2], s_[3]);
            float rm = fmaxf(fmaxf(s_[0], s_[1]), fmaxf(s_[2], s_[3]));
            #pragma unroll
            for (int off = 8; off; off >>= 1)
                rm = fmaxf(rm, __shfl_xor_sync(0xffffffffu, rm, off));
            float newm = fmaxf(m_i[i], rm);
            float rs = 0.f;
            #pragma unroll
            for (int j = 0; j < 4; j++) { p_[i][j] = __expf(s_[j] - newm); rs += p_[i][j]; }
            #pragma unroll
            for (int off = 8; off; off >>= 1)
                rs += __shfl_xor_sync(0xffffffffu, rs, off);
            float corr = __expf(m_i[i] - newm);
            l_i[i] = l_i[i] * corr + rs;
            m_i[i] = newm;
            ull cb = bcast2(corr);
            #pragma unroll
            for (int jp = 0; jp < 5; jp++) mul2(oacc[i][jp], cb);
        }
        // store P transposed: PsT[kk][row], rows contiguous -> float4 stores
        #pragma unroll
        for (int j = 0; j < 4; j++) {
            *(float4*)&PsT[(4*tx + j)*68 + 4*ty] =
                make_float4(p_[0][j], p_[1][j], p_[2][j], p_[3][j]);
        }
        __syncthreads();

        // ---- O += P V, packed over col pairs (cols tx*10 .. tx*10+9) ----
        #pragma unroll 2
        for (int kk = 0; kk < 64; kk++) {
            float4 pr = *(const float4*)&PsT[kk*68 + 4*ty];
            const float* vrow = &Vs[kk*160 + tx*10];
            ull vv[5];
            #pragma unroll
            for (int jp = 0; jp < 5; jp++)
                vv[jp] = *(const ull*)&vrow[2*jp];
            #pragma unroll
            for (int i = 0; i < 4; i++) {
                ull pb = bcast2(((const float*)&pr)[i]);
                #pragma unroll
                for (int jp = 0; jp < 5; jp++)
                    fma2(oacc[i][jp], pb, vv[jp]);
            }
        }
    }

    #pragma unroll
    for (int i = 0; i < 4; i++) {
        float inv = 1.0f / l_i[i];
        float* obase = o + (bbase + q0 + 4*ty + i) * (size_t)DD + hoff;
        #pragma unroll
        for (int jp = 0; jp < 5; jp++) {
            float f0, f1; unpack2(oacc[i][jp], f0, f1);
            int c0 = tx*10 + 2*jp;
            if (c0   < 144) obase[c0  ] = f0 * inv;
            if (c0+1 < 144) obase[c0+1] = f1 * inv;
        }
    }
}

// ====================== epilogue: residual + LN(first 128) + SiLU ======================
__global__ void __launch_bounds__(256) epilogue_kernel(const float* __restrict__ x,
                                                       const float* __restrict__ attn,
                                                       const float* __restrict__ gamma,
                                                       const float* __restrict__ beta,
                                                       float* __restrict__ out)
{
    const int n = blockIdx.x;
    const int tid = threadIdx.x;
    const size_t base = (size_t)n * DD;

    __shared__ float red[8];
    __shared__ float mu_s, rv_s;

    float val = 0.f;
    if (tid < 128) val = x[base + tid] + attn[base + tid];
    float s1 = val, s2 = val * val;
    #pragma unroll
    for (int off = 16; off; off >>= 1) {
        s1 += __shfl_xor_sync(0xffffffffu, s1, off);
        s2 += __shfl_xor_sync(0xffffffffu, s2, off);
    }
    if (tid < 128 && (tid & 31) == 0) { red[(tid>>5)*2] = s1; red[(tid>>5)*2+1] = s2; }
    __syncthreads();
    if (tid == 0) {
        float t1 = red[0] + red[2] + red[4] + red[6];
        float t2 = red[1] + red[3] + red[5] + red[7];
        float mu = t1 * (1.f/128.f);
        float var = t2 * (1.f/128.f) - mu*mu;
        mu_s = mu;
        rv_s = rsqrtf(var + 1e-5f);
    }
    __syncthreads();
    const float mu = mu_s, rv = rv_s;

    for (int i = tid; i < DD; i += 256) {
        float vv = x[base + i] + attn[base + i];
        if (i < 128) {
            float z = (vv - mu) * rv * gamma[i] + beta[i];
            vv = z / (1.f + __expf(-z));
        }
        out[base + i] = vv;
    }
}

// ====================== launch ======================
extern "C" void kernel_launch(void* const* d_in, const int* in_sizes, int n_in,
                              void* d_out, int out_size)
{
    const float* x     = (const float*)d_in[0];
    const float* ev    = (const float*)d_in[1];
    const float* er    = (const float*)d_in[2];
    const float* Wq    = (const float*)d_in[3];
    const float* Wk    = (const float*)d_in[4];
    const float* Wv    = (const float*)d_in[5];
    const float* Wo    = (const float*)d_in[6];
    const float* gamma = (const float*)d_in[7];
    const float* beta  = (const float*)d_in[8];
    float* out  = (float*)d_out;
    float* rotp = out + (size_t)NN * DD;

    float *qp, *kp, *vp, *op;
    cudaGetSymbolAddress((void**)&qp, g_q);
    cudaGetSymbolAddress((void**)&kp, g_k);
    cudaGetSymbolAddress((void**)&vp, g_v);
    cudaGetSymbolAddress((void**)&op, g_o);

    const int SM0 = 128*68*4 + 16*128*4;             // 43008
    const int SM1 = 128*68*4 + 16*384*4;             // 59392
    const int SM2 = 128*68*4 + 16*640*4;             // 75776
    const int SMA = (2*144*68 + 64*160 + 64*68) * 4; // 136704

    cudaFuncSetAttribute((const void*)linear_kernel<0>, cudaFuncAttributeMaxDynamicSharedMemorySize, SM0);
    cudaFuncSetAttribute((const void*)linear_kernel<1>, cudaFuncAttributeMaxDynamicSharedMemorySize, SM1);
    cudaFuncSetAttribute((const void*)linear_kernel<2>, cudaFuncAttributeMaxDynamicSharedMemorySize, SM2);
    cudaFuncSetAttribute((const void*)attn_kernel,      cudaFuncAttributeMaxDynamicSharedMemorySize, SMA);

    rot_kernel<<<EE/256, 256>>>(ev, er, rotp);

    dim3 lgrid(NN/16, 2);
    linear_kernel<0><<<lgrid, 256, SM0>>>(x, Wq, qp);
    linear_kernel<1><<<lgrid, 256, SM1>>>(x, Wq, qp);
    linear_kernel<2><<<lgrid, 256, SM2>>>(x, Wq, qp);
    linear_kernel<0><<<lgrid, 256, SM0>>>(x, Wk, kp);
    linear_kernel<1><<<lgrid, 256, SM1>>>(x, Wk, kp);
    linear_kernel<2><<<lgrid, 256, SM2>>>(x, Wk, kp);
    linear_kernel<0><<<lgrid, 256, SM0>>>(x, Wv, vp);
    linear_kernel<1><<<lgrid, 256, SM1>>>(x, Wv, vp);
    linear_kernel<2><<<lgrid, 256, SM2>>>(x, Wv, vp);

    attn_kernel<<<dim3(8, 128), 256, SMA>>>(qp, kp, vp, op);

    linear_kernel<0><<<lgrid, 256, SM0>>>(op, Wo, kp);
    linear_kernel<1><<<lgrid, 256, SM1>>>(op, Wo, kp);
    linear_kernel<2><<<lgrid, 256, SM2>>>(op, Wo, kp);

    epilogue_kernel<<<NN, 256>>>(x, kp, gamma, beta, out);
}